// round 1
// baseline (speedup 1.0000x reference)
#include <cuda_runtime.h>
#include <cuda_bf16.h>

// Rolling window stats, W=64, F=32 columns.
// out[t, 0:32]=mean, [32:64]=std(pop), [64:96]=min, [96:128]=max, [128:160]=sum
//
// Algorithm: chunked van Herk. For t = 16q + r (r in 0..15):
//   window [t, t+63] = suffix(chunk q, from r) ⊕ chunks q+1..q+3 ⊕ prefix(chunk q+4, r elems)
// Thread = (column, 64-output block). Per group of 16 outputs:
//   - M = a0⊕a1⊕a2 (middle chunk aggregates, rolled across groups)
//   - backward pass builds H[r] = M ⊕ suffix(head chunk)  (registers, unrolled)
//   - forward streaming tail accumulator; same accumulator becomes the next
//     middle chunk aggregate A_{q+4} after 16 steps.
// No shared memory, no syncs. Warp = 32 cols of one block -> all loads are
// single coalesced 128B rows, all stores coalesced 128B segments.

#define F 32
#define OUT_STRIDE 160

__global__ __launch_bounds__(256)
void rolling_stats_kernel(const float* __restrict__ x,
                          float* __restrict__ out,
                          int N, int Nout) {
    const int tid = blockIdx.x * blockDim.x + threadIdx.x;
    const int col = tid & 31;
    const int blk = tid >> 5;
    const int t0 = blk * 64;
    if (t0 >= Nout) return;

    const float* __restrict__ xc = x + col;
    const float INF = __int_as_float(0x7f800000);
    const float inv = 1.0f / 64.0f;

    // clamped column load (clamp is only ever hit for rows feeding invalid outputs)
    auto LD = [&](int r) -> float {
        r = min(r, N - 1);
        return __ldg(xc + (size_t)r * F);
    };

    // middle chunk aggregates: chunks covering rows [t0+16, t0+64)
    float a_s[3], a_q[3], a_mn[3], a_mx[3];
#pragma unroll
    for (int c = 0; c < 3; c++) {
        float s = 0.f, q = 0.f, mn = INF, mx = -INF;
        const int base = t0 + 16 + c * 16;
#pragma unroll
        for (int j = 0; j < 16; j++) {
            float v = LD(base + j);
            s += v;
            q = fmaf(v, v, q);
            mn = fminf(mn, v);
            mx = fmaxf(mx, v);
        }
        a_s[c] = s; a_q[c] = q; a_mn[c] = mn; a_mx[c] = mx;
    }

#pragma unroll
    for (int g = 0; g < 4; g++) {
        const int hbase = t0 + g * 16;   // head chunk rows [hbase, hbase+16)
        const int tbase = hbase + 64;    // tail chunk rows [tbase, tbase+16)

        // M = a0 ⊕ a1 ⊕ a2
        const float M_s  = a_s[0] + a_s[1] + a_s[2];
        const float M_q  = a_q[0] + a_q[1] + a_q[2];
        const float M_mn = fminf(a_mn[0], fminf(a_mn[1], a_mn[2]));
        const float M_mx = fmaxf(a_mx[0], fmaxf(a_mx[1], a_mx[2]));

        // head values
        float hv[16];
#pragma unroll
        for (int j = 0; j < 16; j++) hv[j] = LD(hbase + j);

        // H[r] = M ⊕ suffix(hv[r..15]), built backward (stays in registers)
        float H_s[16], H_q[16], H_mn[16], H_mx[16];
        {
            float s = M_s, q = M_q, mn = M_mn, mx = M_mx;
#pragma unroll
            for (int j = 15; j >= 0; j--) {
                const float v = hv[j];
                s += v;
                q = fmaf(v, v, q);
                mn = fminf(mn, v);
                mx = fmaxf(mx, v);
                H_s[j] = s; H_q[j] = q; H_mn[j] = mn; H_mx[j] = mx;
            }
        }

        // streaming tail accumulator (identity-seeded; becomes A_{q+4})
        float t_s = 0.f, t_q = 0.f, t_mn = INF, t_mx = -INF;
#pragma unroll
        for (int r = 0; r < 16; r++) {
            const int t = hbase + r;
            const float S  = H_s[r] + t_s;
            const float Q  = H_q[r] + t_q;
            const float mn = fminf(H_mn[r], t_mn);
            const float mx = fmaxf(H_mx[r], t_mx);
            if (t < Nout) {
                const float mean = S * inv;
                const float var  = fmaf(Q, inv, -(mean * mean));
                const float sd   = sqrtf(fmaxf(var, 0.0f));
                float* o = out + (size_t)t * OUT_STRIDE + col;
                o[0]   = mean;
                o[32]  = sd;
                o[64]  = mn;
                o[96]  = mx;
                o[128] = S;
            }
            // consume tail element r (feeds outputs r+1..15 and A_{q+4})
            const float w = LD(tbase + r);
            t_s += w;
            t_q = fmaf(w, w, t_q);
            t_mn = fminf(t_mn, w);
            t_mx = fmaxf(t_mx, w);
        }

        // roll middle chunk window
        a_s[0] = a_s[1]; a_q[0] = a_q[1]; a_mn[0] = a_mn[1]; a_mx[0] = a_mx[1];
        a_s[1] = a_s[2]; a_q[1] = a_q[2]; a_mn[1] = a_mn[2]; a_mx[1] = a_mx[2];
        a_s[2] = t_s;    a_q[2] = t_q;    a_mn[2] = t_mn;    a_mx[2] = t_mx;
    }
}

extern "C" void kernel_launch(void* const* d_in, const int* in_sizes, int n_in,
                              void* d_out, int out_size) {
    const float* x = (const float*)d_in[0];
    float* out = (float*)d_out;
    const int total = in_sizes[0];
    const int N = total / F;        // 262144 rows
    const int Nout = N - 63;        // 262081 output rows
    const int nblk = (Nout + 63) / 64;
    const int nthreads = nblk * 32;
    const int block = 256;
    const int grid = (nthreads + block - 1) / block;
    rolling_stats_kernel<<<grid, block>>>(x, out, N, Nout);
}

// round 2
// speedup vs baseline: 1.7660x; 1.7660x over previous
#include <cuda_runtime.h>
#include <cuda_bf16.h>

// Rolling window stats, W=64, F=32 columns.
// out[t, 0:32]=mean, [32:64]=std(pop), [64:96]=min, [96:128]=max, [128:160]=sum
//
// Chunked van Herk (chunk=16) with HALF-GROUP register blocking:
// For t = 16q + r: window = suffix(chunk q, r) ⊕ chunks q+1..q+3 ⊕ prefix(chunk q+4, r)
//   M  = a1⊕a2⊕a3 (middle aggregate)
//   M8 = M ⊕ agg(head[8..15])
//   r in 0..7 : H[r] = M8 ⊕ suffix(head[r..7])   (only 8 H-slots live)
//   r in 8..15: H[r] = M  ⊕ suffix(head[r..15])  (same 8 H-slots reused)
// Tail prefix streams forward through both halves and becomes the next
// middle-chunk aggregate. Register footprint ~80 (was 246) -> 5 CTAs/SM.

#define F 32
#define OUT_STRIDE 160

__global__ __launch_bounds__(128, 5)
void rolling_stats_kernel(const float* __restrict__ x,
                          float* __restrict__ out,
                          int N, int Nout) {
    const int tid = blockIdx.x * blockDim.x + threadIdx.x;
    const int col = tid & 31;
    const int blk = tid >> 5;
    const int t0 = blk * 64;
    if (t0 >= Nout) return;

    const float* __restrict__ xc = x + col;
    const float INF = __int_as_float(0x7f800000);
    const float inv = 1.0f / 64.0f;
    const int nclamp = N - 1;

    auto LD = [&](int r) -> float {
        r = min(r, nclamp);
        return __ldg(xc + (size_t)r * F);
    };

    // middle chunk aggregates: rows [t0+16, t0+64)
    float a_s[3], a_q[3], a_mn[3], a_mx[3];
#pragma unroll
    for (int c = 0; c < 3; c++) {
        float s = 0.f, q = 0.f, mn = INF, mx = -INF;
        const int base = t0 + 16 + c * 16;
#pragma unroll
        for (int j = 0; j < 16; j++) {
            float v = LD(base + j);
            s += v; q = fmaf(v, v, q);
            mn = fminf(mn, v); mx = fmaxf(mx, v);
        }
        a_s[c] = s; a_q[c] = q; a_mn[c] = mn; a_mx[c] = mx;
    }

#pragma unroll
    for (int g = 0; g < 4; g++) {
        const int hbase = t0 + g * 16;   // head chunk rows [hbase, hbase+16)
        const int tbase = hbase + 64;    // tail chunk rows [tbase, tbase+16)

        // M = a0 ⊕ a1 ⊕ a2  (a0 dead afterwards)
        const float M_s  = a_s[0] + a_s[1] + a_s[2];
        const float M_q  = a_q[0] + a_q[1] + a_q[2];
        const float M_mn = fminf(a_mn[0], fminf(a_mn[1], a_mn[2]));
        const float M_mx = fmaxf(a_mx[0], fmaxf(a_mx[1], a_mx[2]));

        // load head (batched, MLP=16)
        float hlo[8], hhi[8];
#pragma unroll
        for (int j = 0; j < 8; j++) hlo[j] = LD(hbase + j);
#pragma unroll
        for (int j = 0; j < 8; j++) hhi[j] = LD(hbase + 8 + j);

        // M8 = M ⊕ agg(head[8..15])
        float M8_s = M_s, M8_q = M_q, M8_mn = M_mn, M8_mx = M_mx;
#pragma unroll
        for (int j = 0; j < 8; j++) {
            const float v = hhi[j];
            M8_s += v; M8_q = fmaf(v, v, M8_q);
            M8_mn = fminf(M8_mn, v); M8_mx = fmaxf(M8_mx, v);
        }

        // streaming tail accumulator (identity-seeded; becomes next chunk agg)
        float t_s = 0.f, t_q = 0.f, t_mn = INF, t_mx = -INF;

        float H_s[8], H_q[8], H_mn[8], H_mx[8];

        // ---- first half: r = 0..7, H[r] = M8 ⊕ suffix(hlo[r..7]) ----
        {
            float s = M8_s, q = M8_q, mn = M8_mn, mx = M8_mx;
#pragma unroll
            for (int j = 7; j >= 0; j--) {
                const float v = hlo[j];
                s += v; q = fmaf(v, v, q);
                mn = fminf(mn, v); mx = fmaxf(mx, v);
                H_s[j] = s; H_q[j] = q; H_mn[j] = mn; H_mx[j] = mx;
            }
        }
        {
            float w[8];
#pragma unroll
            for (int j = 0; j < 8; j++) w[j] = LD(tbase + j);
#pragma unroll
            for (int r = 0; r < 8; r++) {
                const int t = hbase + r;
                const float S  = H_s[r] + t_s;
                const float Q  = H_q[r] + t_q;
                const float mn = fminf(H_mn[r], t_mn);
                const float mx = fmaxf(H_mx[r], t_mx);
                if (t < Nout) {
                    const float mean = S * inv;
                    const float var  = fmaf(Q, inv, -(mean * mean));
                    const float sd   = sqrtf(fmaxf(var, 0.0f));
                    float* o = out + (size_t)t * OUT_STRIDE + col;
                    o[0]   = mean;
                    o[32]  = sd;
                    o[64]  = mn;
                    o[96]  = mx;
                    o[128] = S;
                }
                const float v = w[r];
                t_s += v; t_q = fmaf(v, v, t_q);
                t_mn = fminf(t_mn, v); t_mx = fmaxf(t_mx, v);
            }
        }

        // ---- second half: r = 8..15, H[r-8] = M ⊕ suffix(hhi[r-8..7]) ----
        {
            float s = M_s, q = M_q, mn = M_mn, mx = M_mx;
#pragma unroll
            for (int j = 7; j >= 0; j--) {
                const float v = hhi[j];
                s += v; q = fmaf(v, v, q);
                mn = fminf(mn, v); mx = fmaxf(mx, v);
                H_s[j] = s; H_q[j] = q; H_mn[j] = mn; H_mx[j] = mx;
            }
        }
        {
            float w[8];
#pragma unroll
            for (int j = 0; j < 8; j++) w[j] = LD(tbase + 8 + j);
#pragma unroll
            for (int r = 0; r < 8; r++) {
                const int t = hbase + 8 + r;
                const float S  = H_s[r] + t_s;
                const float Q  = H_q[r] + t_q;
                const float mn = fminf(H_mn[r], t_mn);
                const float mx = fmaxf(H_mx[r], t_mx);
                if (t < Nout) {
                    const float mean = S * inv;
                    const float var  = fmaf(Q, inv, -(mean * mean));
                    const float sd   = sqrtf(fmaxf(var, 0.0f));
                    float* o = out + (size_t)t * OUT_STRIDE + col;
                    o[0]   = mean;
                    o[32]  = sd;
                    o[64]  = mn;
                    o[96]  = mx;
                    o[128] = S;
                }
                const float v = w[r];
                t_s += v; t_q = fmaf(v, v, t_q);
                t_mn = fminf(t_mn, v); t_mx = fmaxf(t_mx, v);
            }
        }

        // roll middle chunk window
        a_s[0] = a_s[1]; a_q[0] = a_q[1]; a_mn[0] = a_mn[1]; a_mx[0] = a_mx[1];
        a_s[1] = a_s[2]; a_q[1] = a_q[2]; a_mn[1] = a_mn[2]; a_mx[1] = a_mx[2];
        a_s[2] = t_s;    a_q[2] = t_q;    a_mn[2] = t_mn;    a_mx[2] = t_mx;
    }
}

extern "C" void kernel_launch(void* const* d_in, const int* in_sizes, int n_in,
                              void* d_out, int out_size) {
    const float* x = (const float*)d_in[0];
    float* out = (float*)d_out;
    const int total = in_sizes[0];
    const int N = total / F;        // 262144 rows
    const int Nout = N - 63;        // 262081 output rows
    const int nblk = (Nout + 63) / 64;   // 64 outputs per thread-tile
    const int nthreads = nblk * 32;
    const int block = 128;
    const int grid = (nthreads + block - 1) / block;
    rolling_stats_kernel<<<grid, block>>>(x, out, N, Nout);
}